// round 10
// baseline (speedup 1.0000x reference)
#include <cuda_runtime.h>
#include <cuda_fp16.h>

#define LEN_Q   13294
#define NQ      (2 * LEN_Q)     // 26588 rows (b*LEN_Q + q)
#define N_OUT   384             // 256 offset cols + 128 attn cols
#define RB      8               // rows per sampler block (512 threads)
#define GEMM_MBLKS 208          // ceil(NQ/128)
#define GEMM_BLOCKS (GEMM_MBLKS * 3)
#define CVT_BLOCKS  (NQ * 256 / 4 / 256)   // 6647 exactly

// Scratch: projection output P[NQ][384]; fp16 copy of value
__device__ float  g_P[NQ * N_OUT];
__device__ __half g_Vh[(size_t)NQ * 256];

// ---------------------------------------------------------------------------
// mma / cp.async helpers
// ---------------------------------------------------------------------------
__device__ __forceinline__ void mma_tf32(float* d, const unsigned* a, const unsigned* b) {
    asm volatile(
        "mma.sync.aligned.m16n8k8.row.col.f32.tf32.tf32.f32 "
        "{%0,%1,%2,%3}, {%4,%5,%6,%7}, {%8,%9}, {%0,%1,%2,%3};"
        : "+f"(d[0]), "+f"(d[1]), "+f"(d[2]), "+f"(d[3])
        : "r"(a[0]), "r"(a[1]), "r"(a[2]), "r"(a[3]),
          "r"(b[0]), "r"(b[1]));
}
__device__ __forceinline__ unsigned smem_u32(const void* p) {
    return (unsigned)__cvta_generic_to_shared(p);
}
__device__ __forceinline__ void cp_async16(unsigned dst, const void* src, int src_bytes) {
    asm volatile("cp.async.ca.shared.global [%0], [%1], 16, %2;"
                 :: "r"(dst), "l"(src), "r"(src_bytes));
}
__device__ __forceinline__ void cp_commit() {
    asm volatile("cp.async.commit_group;");
}
template <int N>
__device__ __forceinline__ void cp_wait() {
    asm volatile("cp.async.wait_group %0;" :: "n"(N));
}

// ---------------------------------------------------------------------------
// Fused kernel: blocks [0, GEMM_BLOCKS) = tf32 GEMM; rest = value fp32->fp16.
// GEMM v5: raw fp32 bits fed to tf32 mma (HW truncates mantissa — no CVTs),
// LDB=136 for conflict-free B fragments.
// ---------------------------------------------------------------------------
#define LDA 20     // 16 + 4 pad (floats): A frags conflict-free (g*20+tig perm)
#define LDB 136    // 128 + 8 pad (floats): 136 % 32 == 8 -> tig*8+g perm

__global__ __launch_bounds__(256) void msda_gemm_cvt_kernel(
    const float* __restrict__ Q,
    const float* __restrict__ Woff, const float* __restrict__ boff,
    const float* __restrict__ Wattn, const float* __restrict__ battn,
    const float* __restrict__ value)
{
    // ---- cvt part -----------------------------------------------------
    if (blockIdx.x >= GEMM_BLOCKS) {
        const int i = (blockIdx.x - GEMM_BLOCKS) * 256 + threadIdx.x;  // float4 idx
        const float4 f = ((const float4*)value)[i];
        __half2* dst = (__half2*)g_Vh + (size_t)i * 2;
        dst[0] = __floats2half2_rn(f.x, f.y);
        dst[1] = __floats2half2_rn(f.z, f.w);
        return;
    }

    // ---- GEMM part ----------------------------------------------------
    __shared__ float As[2][128 * LDA];   // [m][k]
    __shared__ float Bs[2][16 * LDB];    // [k][n]

    const int mblk = blockIdx.x % GEMM_MBLKS;
    const int nblk = blockIdx.x / GEMM_MBLKS;
    const int m0   = mblk * 128;

    const float* W; const float* bias; int ldW, n0;
    if (nblk < 2) { W = Woff;  bias = boff + nblk * 128; ldW = 256; n0 = nblk * 128; }
    else          { W = Wattn; bias = battn;             ldW = 128; n0 = 0;          }
    const int outn0 = nblk * 128;

    const int tid  = threadIdx.x;
    const int wid  = tid >> 5;
    const int lane = tid & 31;
    const int g    = lane >> 2;
    const int tig  = lane & 3;
    const int wm   = wid & 1;
    const int wn   = wid >> 1;

    const int ac0r = tid >> 2,         ac0k = (tid & 3) * 4;
    const int ac1r = (tid + 256) >> 2, ac1k = ((tid + 256) & 3) * 4;
    const int bc0r = tid >> 5,         bc0c = (tid & 31) * 4;
    const int bc1r = (tid + 256) >> 5, bc1c = ((tid + 256) & 31) * 4;

    const unsigned sA[2] = { smem_u32(&As[0][0]), smem_u32(&As[1][0]) };
    const unsigned sB[2] = { smem_u32(&Bs[0][0]), smem_u32(&Bs[1][0]) };

    auto load_tile = [&](int s, int k0) {
        int v0 = (m0 + ac0r < NQ) ? 16 : 0;
        int v1 = (m0 + ac1r < NQ) ? 16 : 0;
        cp_async16(sA[s] + (ac0r * LDA + ac0k) * 4,
                   &Q[(size_t)(m0 + ac0r) * 256 + k0 + ac0k], v0);
        cp_async16(sA[s] + (ac1r * LDA + ac1k) * 4,
                   &Q[(size_t)(m0 + ac1r) * 256 + k0 + ac1k], v1);
        cp_async16(sB[s] + (bc0r * LDB + bc0c) * 4,
                   &W[(size_t)(k0 + bc0r) * ldW + n0 + bc0c], 16);
        cp_async16(sB[s] + (bc1r * LDB + bc1c) * 4,
                   &W[(size_t)(k0 + bc1r) * ldW + n0 + bc1c], 16);
        cp_commit();
    };

    float acc[4][4][4];
#pragma unroll
    for (int tm = 0; tm < 4; tm++)
#pragma unroll
        for (int tn = 0; tn < 4; tn++)
#pragma unroll
            for (int r = 0; r < 4; r++) acc[tm][tn][r] = 0.f;

    load_tile(0, 0);

    const unsigned* Au[2] = { (const unsigned*)&As[0][0], (const unsigned*)&As[1][0] };
    const unsigned* Bu[2] = { (const unsigned*)&Bs[0][0], (const unsigned*)&Bs[1][0] };

#pragma unroll 1
    for (int it = 0; it < 16; it++) {
        const int s = it & 1;
        if (it + 1 < 16) {
            load_tile(1 - s, (it + 1) * 16);
            cp_wait<1>();
        } else {
            cp_wait<0>();
        }
        __syncthreads();

        const unsigned* Ab = Au[s];
        const unsigned* Bb = Bu[s];
#pragma unroll
        for (int ks = 0; ks < 2; ks++) {
            const int kk = ks * 8;
            unsigned af[4][4];
#pragma unroll
            for (int tm = 0; tm < 4; tm++) {
                const int r = wm * 64 + tm * 16;
                af[tm][0] = Ab[(r + g)     * LDA + kk + tig];
                af[tm][1] = Ab[(r + g + 8) * LDA + kk + tig];
                af[tm][2] = Ab[(r + g)     * LDA + kk + tig + 4];
                af[tm][3] = Ab[(r + g + 8) * LDA + kk + tig + 4];
            }
            unsigned bf[4][2];
#pragma unroll
            for (int tn = 0; tn < 4; tn++) {
                const int c = wn * 32 + tn * 8;
                bf[tn][0] = Bb[(kk + tig)     * LDB + c + g];
                bf[tn][1] = Bb[(kk + tig + 4) * LDB + c + g];
            }
#pragma unroll
            for (int tm = 0; tm < 4; tm++)
#pragma unroll
                for (int tn = 0; tn < 4; tn++)
                    mma_tf32(acc[tm][tn], af[tm], bf[tn]);
        }
        __syncthreads();
    }

#pragma unroll
    for (int tn = 0; tn < 4; tn++) {
        const int cl = wn * 32 + tn * 8 + tig * 2;
        const float2 bv = *(const float2*)&bias[cl];
#pragma unroll
        for (int tm = 0; tm < 4; tm++) {
            const int r0 = m0 + wm * 64 + tm * 16 + g;
            const int r1 = r0 + 8;
            if (r0 < NQ) {
                float2 o = make_float2(acc[tm][tn][0] + bv.x, acc[tm][tn][1] + bv.y);
                *(float2*)&g_P[(size_t)r0 * N_OUT + outn0 + cl] = o;
            }
            if (r1 < NQ) {
                float2 o = make_float2(acc[tm][tn][2] + bv.x, acc[tm][tn][3] + bv.y);
                *(float2*)&g_P[(size_t)r1 * N_OUT + outn0 + cl] = o;
            }
        }
    }
}

// ---------------------------------------------------------------------------
// Sampling v5 (unchanged from R9: 77.7us, occ 92%, at L1 ceiling).
// ---------------------------------------------------------------------------
__global__ __launch_bounds__(512) void msda_sample_kernel(
    const float* __restrict__ ref,    // (2, LEN_Q, 4, 2)
    float* __restrict__ out)          // (2, LEN_Q, 256)
{
    __shared__ float4 s_w[RB][8][17];   // padded: head stride 17
    __shared__ int    s_i[RB][8][17];

    const int row0 = blockIdx.x * RB;
    const int t    = threadIdx.x;

    // ---------------- Phase 1: 8 threads per (row, head), 2 points each ----
    {
        const int pair = t >> 3;        // 0..63: (row_local, head)
        const int sub  = t & 7;         // 2 points each
        const int rl   = pair >> 3;
        const int h    = pair & 7;
        const int row  = row0 + rl;

        if (row < NQ) {
            const float* Prow = g_P + (size_t)row * N_OUT;

            float lg[16];
#pragma unroll
            for (int v = 0; v < 4; v++) {
                float4 q = *(const float4*)&Prow[256 + h * 16 + v * 4];
                lg[v*4+0] = q.x; lg[v*4+1] = q.y; lg[v*4+2] = q.z; lg[v*4+3] = q.w;
            }
            float mx = lg[0];
#pragma unroll
            for (int v = 1; v < 16; v++) mx = fmaxf(mx, lg[v]);
            float ssum = 0.f;
#pragma unroll
            for (int v = 0; v < 16; v++) ssum += __expf(lg[v] - mx);
            const float inv = 1.f / ssum;

#pragma unroll
            for (int jj = 0; jj < 2; jj++) {
                const int j = sub * 2 + jj;
                const int l = j >> 2;
                const int D = (l == 0) ? 100 : (l == 1) ? 50 : (l == 2) ? 25 : 13;

                const float wgt  = __expf(lg[j] - mx) * inv;
                const float offx = Prow[h * 32 + j * 2];
                const float offy = Prow[h * 32 + j * 2 + 1];
                const float rx = ref[(size_t)(row * 4 + l) * 2 + 0];
                const float ry = ref[(size_t)(row * 4 + l) * 2 + 1];
                const float x = fmaf(rx, (float)D, offx) - 0.5f;
                const float y = fmaf(ry, (float)D, offy) - 0.5f;

                const float xf = floorf(x), yf = floorf(y);
                const int x0 = (int)xf, y0 = (int)yf;
                const float fx = x - xf, fy = y - yf;

                const float gx0 = (x0 >= 0     && x0 < D)     ? (1.f - fx) : 0.f;
                const float gx1 = (x0 + 1 >= 0 && x0 + 1 < D) ? fx         : 0.f;
                const float gy0 = (y0 >= 0     && y0 < D)     ? (1.f - fy) : 0.f;
                const float gy1 = (y0 + 1 >= 0 && y0 + 1 < D) ? fy         : 0.f;

                const int cx = min(max(x0, 0), D - 2);
                const int cy = min(max(y0, 0), D - 2);
                const float wl = (x0 < 0) ? gx1 : ((x0 <= D - 2) ? gx0 : 0.f);
                const float wr = (x0 < 0) ? 0.f : ((x0 <= D - 2) ? gx1 : gx0);
                const float wt = (y0 < 0) ? gy1 : ((y0 <= D - 2) ? gy0 : 0.f);
                const float wb = (y0 < 0) ? 0.f : ((y0 <= D - 2) ? gy1 : gy0);

                s_w[rl][h][j] = make_float4(wgt * wl * wt, wgt * wr * wt,
                                            wgt * wl * wb, wgt * wr * wb);
                s_i[rl][h][j] = cy * D + cx;
            }
        }
    }
    __syncthreads();

    // ---------------- Phase 2: one float4-slot per thread ----------------
    {
        const int rl  = t >> 6;              // 0..7
        const int c4  = t & 63;              // float4 slot: head = c4>>3
        const int row = row0 + rl;
        if (row >= NQ) return;

        const int h = c4 >> 3;
        const int b = (row >= LEN_Q) ? 1 : 0;
        const __half* vb = g_Vh + (size_t)b * LEN_Q * 256 + h * 32 + (c4 & 7) * 4;

        float4 acc = make_float4(0.f, 0.f, 0.f, 0.f);
#pragma unroll
        for (int j = 0; j < 16; j++) {
            const int l    = j >> 2;                          // compile-time
            const int DD   = (l == 0) ? 100 : (l == 1) ? 50 : (l == 2) ? 25 : 13;
            const int BASE = (l == 0) ? 0 : (l == 1) ? 10000 : (l == 2) ? 12500 : 13125;

            const float4 w  = s_w[rl][h][j];
            const int    ix = s_i[rl][h][j];
            const __half* p = vb + (size_t)(BASE + ix) * 256;

            const uint2 u00 = *(const uint2*)p;
            const uint2 u01 = *(const uint2*)(p + 256);
            const uint2 u10 = *(const uint2*)(p + DD * 256);
            const uint2 u11 = *(const uint2*)(p + DD * 256 + 256);

            const float2 a00 = __half22float2(*(const __half2*)&u00.x);
            const float2 b00 = __half22float2(*(const __half2*)&u00.y);
            const float2 a01 = __half22float2(*(const __half2*)&u01.x);
            const float2 b01 = __half22float2(*(const __half2*)&u01.y);
            const float2 a10 = __half22float2(*(const __half2*)&u10.x);
            const float2 b10 = __half22float2(*(const __half2*)&u10.y);
            const float2 a11 = __half22float2(*(const __half2*)&u11.x);
            const float2 b11 = __half22float2(*(const __half2*)&u11.y);

            acc.x = fmaf(w.x, a00.x, acc.x);
            acc.y = fmaf(w.x, a00.y, acc.y);
            acc.z = fmaf(w.x, b00.x, acc.z);
            acc.w = fmaf(w.x, b00.y, acc.w);
            acc.x = fmaf(w.y, a01.x, acc.x);
            acc.y = fmaf(w.y, a01.y, acc.y);
            acc.z = fmaf(w.y, b01.x, acc.z);
            acc.w = fmaf(w.y, b01.y, acc.w);
            acc.x = fmaf(w.z, a10.x, acc.x);
            acc.y = fmaf(w.z, a10.y, acc.y);
            acc.z = fmaf(w.z, b10.x, acc.z);
            acc.w = fmaf(w.z, b10.y, acc.w);
            acc.x = fmaf(w.w, a11.x, acc.x);
            acc.y = fmaf(w.w, a11.y, acc.y);
            acc.z = fmaf(w.w, b11.x, acc.z);
            acc.w = fmaf(w.w, b11.y, acc.w);
        }

        *(float4*)&out[(size_t)row * 256 + c4 * 4] = acc;
    }
}

// ---------------------------------------------------------------------------
extern "C" void kernel_launch(void* const* d_in, const int* in_sizes, int n_in,
                              void* d_out, int out_size)
{
    const float* query = (const float*)d_in[0];   // (2, LEN_Q, 256)
    const float* ref   = (const float*)d_in[1];   // (2, LEN_Q, 4, 2)
    const float* value = (const float*)d_in[2];   // (2, LEN_Q, 256)
    const float* Woff  = (const float*)d_in[3];   // (256, 256)
    const float* boff  = (const float*)d_in[4];   // (256,)
    const float* Wattn = (const float*)d_in[5];   // (256, 128)
    const float* battn = (const float*)d_in[6];   // (128,)
    float* out = (float*)d_out;                   // (2, LEN_Q, 256)

    msda_gemm_cvt_kernel<<<GEMM_BLOCKS + CVT_BLOCKS, 256>>>(
        query, Woff, boff, Wattn, battn, value);

    const int nblocks = (NQ + RB - 1) / RB;       // 3324
    msda_sample_kernel<<<nblocks, 512>>>(ref, out);
}

// round 14
// speedup vs baseline: 1.0292x; 1.0292x over previous
#include <cuda_runtime.h>
#include <cuda_fp16.h>

#define LEN_Q   13294
#define NQ      (2 * LEN_Q)     // 26588 rows (b*LEN_Q + q)
#define N_OUT   384             // 256 offset cols + 128 attn cols
#define RB      8               // rows per sampler block (512 threads)
#define GEMM_MBLKS 208          // ceil(NQ/128)
#define GEMM_BLOCKS (GEMM_MBLKS * 3)
#define CVT_BLOCKS  (NQ * 256 / 4 / 256)   // 6647 exactly

#define LDA 20     // 16 + 4 pad (floats)
#define LDB 132    // 128 + 4 pad (floats)

// Scratch: projection output P[NQ][384]; fp16 copy of value
__device__ float  g_P[NQ * N_OUT];
__device__ __half g_Vh[(size_t)NQ * 256];

// ---------------------------------------------------------------------------
// tf32 / cp.async helpers
// ---------------------------------------------------------------------------
__device__ __forceinline__ unsigned f2tf32(float f) {
    unsigned u;
    asm("cvt.rna.tf32.f32 %0, %1;" : "=r"(u) : "f"(f));
    return u;
}
__device__ __forceinline__ void mma_tf32(float* d, const unsigned* a, const unsigned* b) {
    asm volatile(
        "mma.sync.aligned.m16n8k8.row.col.f32.tf32.tf32.f32 "
        "{%0,%1,%2,%3}, {%4,%5,%6,%7}, {%8,%9}, {%0,%1,%2,%3};"
        : "+f"(d[0]), "+f"(d[1]), "+f"(d[2]), "+f"(d[3])
        : "r"(a[0]), "r"(a[1]), "r"(a[2]), "r"(a[3]),
          "r"(b[0]), "r"(b[1]));
}
__device__ __forceinline__ unsigned smem_u32(const void* p) {
    return (unsigned)__cvta_generic_to_shared(p);
}
__device__ __forceinline__ void cp_async16(unsigned dst, const void* src, int src_bytes) {
    asm volatile("cp.async.cg.shared.global [%0], [%1], 16, %2;"
                 :: "r"(dst), "l"(src), "r"(src_bytes));
}
__device__ __forceinline__ void cp_commit() {
    asm volatile("cp.async.commit_group;");
}
template <int N>
__device__ __forceinline__ void cp_wait() {
    asm volatile("cp.async.wait_group %0;" :: "n"(N));
}

// ---------------------------------------------------------------------------
// Fused kernel: blocks [0, GEMM_BLOCKS) = tf32 GEMM; rest = value fp32->fp16.
// GEMM v7: 2-stage cp.async pipeline, ONE __syncthreads per iteration
// (wait -> sync -> issue-next -> compute). Static smem 37.4KB. R9 numerics.
// ---------------------------------------------------------------------------
__global__ __launch_bounds__(256) void msda_gemm_cvt_kernel(
    const float* __restrict__ Q,
    const float* __restrict__ Woff, const float* __restrict__ boff,
    const float* __restrict__ Wattn, const float* __restrict__ battn,
    const float* __restrict__ value)
{
    // ---- cvt part -----------------------------------------------------
    if (blockIdx.x >= GEMM_BLOCKS) {
        const int i = (blockIdx.x - GEMM_BLOCKS) * 256 + threadIdx.x;  // float4 idx
        const float4 f = ((const float4*)value)[i];
        __half2* dst = (__half2*)g_Vh + (size_t)i * 2;
        dst[0] = __floats2half2_rn(f.x, f.y);
        dst[1] = __floats2half2_rn(f.z, f.w);
        return;
    }

    // ---- GEMM part ----------------------------------------------------
    __shared__ float As[2][128 * LDA];   // [m][k]
    __shared__ float Bs[2][16 * LDB];    // [k][n]

    const int mblk = blockIdx.x % GEMM_MBLKS;
    const int nblk = blockIdx.x / GEMM_MBLKS;
    const int m0   = mblk * 128;

    const float* W; const float* bias; int ldW, n0;
    if (nblk < 2) { W = Woff;  bias = boff + nblk * 128; ldW = 256; n0 = nblk * 128; }
    else          { W = Wattn; bias = battn;             ldW = 128; n0 = 0;          }
    const int outn0 = nblk * 128;

    const int tid  = threadIdx.x;
    const int wid  = tid >> 5;
    const int lane = tid & 31;
    const int g    = lane >> 2;
    const int tig  = lane & 3;
    const int wm   = wid & 1;
    const int wn   = wid >> 1;

    const int ac0r = tid >> 2,         ac0k = (tid & 3) * 4;
    const int ac1r = (tid + 256) >> 2, ac1k = ((tid + 256) & 3) * 4;
    const int bc0r = tid >> 5,         bc0c = (tid & 31) * 4;
    const int bc1r = (tid + 256) >> 5, bc1c = ((tid + 256) & 31) * 4;

    const unsigned sA[2] = { smem_u32(&As[0][0]), smem_u32(&As[1][0]) };
    const unsigned sB[2] = { smem_u32(&Bs[0][0]), smem_u32(&Bs[1][0]) };

    auto load_tile = [&](int s, int k0) {
        int v0 = (m0 + ac0r < NQ) ? 16 : 0;
        int v1 = (m0 + ac1r < NQ) ? 16 : 0;
        cp_async16(sA[s] + (ac0r * LDA + ac0k) * 4,
                   &Q[(size_t)(m0 + ac0r) * 256 + k0 + ac0k], v0);
        cp_async16(sA[s] + (ac1r * LDA + ac1k) * 4,
                   &Q[(size_t)(m0 + ac1r) * 256 + k0 + ac1k], v1);
        cp_async16(sB[s] + (bc0r * LDB + bc0c) * 4,
                   &W[(size_t)(k0 + bc0r) * ldW + n0 + bc0c], 16);
        cp_async16(sB[s] + (bc1r * LDB + bc1c) * 4,
                   &W[(size_t)(k0 + bc1r) * ldW + n0 + bc1c], 16);
        cp_commit();
    };

    float acc[4][4][4];
#pragma unroll
    for (int tm = 0; tm < 4; tm++)
#pragma unroll
        for (int tn = 0; tn < 4; tn++)
#pragma unroll
            for (int r = 0; r < 4; r++) acc[tm][tn][r] = 0.f;

    load_tile(0, 0);

#pragma unroll 1
    for (int it = 0; it < 16; it++) {
        cp_wait<0>();             // tile `it` landed (per-thread)
        __syncthreads();          // cross-thread visibility + iter it-1 reads done

        if (it + 1 < 16) load_tile((it + 1) & 1, (it + 1) * 16);

        const int s = it & 1;
        const float* Ab = &As[s][0];
        const float* Bb = &Bs[s][0];
#pragma unroll
        for (int ks = 0; ks < 2; ks++) {
            const int kk = ks * 8;
            unsigned af[4][4];
#pragma unroll
            for (int tm = 0; tm < 4; tm++) {
                const int r = wm * 64 + tm * 16;
                af[tm][0] = f2tf32(Ab[(r + g)     * LDA + kk + tig]);
                af[tm][1] = f2tf32(Ab[(r + g + 8) * LDA + kk + tig]);
                af[tm][2] = f2tf32(Ab[(r + g)     * LDA + kk + tig + 4]);
                af[tm][3] = f2tf32(Ab[(r + g + 8) * LDA + kk + tig + 4]);
            }
            unsigned bf[4][2];
#pragma unroll
            for (int tn = 0; tn < 4; tn++) {
                const int c = wn * 32 + tn * 8;
                bf[tn][0] = f2tf32(Bb[(kk + tig)     * LDB + c + g]);
                bf[tn][1] = f2tf32(Bb[(kk + tig + 4) * LDB + c + g]);
            }
#pragma unroll
            for (int tm = 0; tm < 4; tm++)
#pragma unroll
                for (int tn = 0; tn < 4; tn++)
                    mma_tf32(acc[tm][tn], af[tm], bf[tn]);
        }
    }

#pragma unroll
    for (int tn = 0; tn < 4; tn++) {
        const int cl = wn * 32 + tn * 8 + tig * 2;
        const float2 bv = *(const float2*)&bias[cl];
#pragma unroll
        for (int tm = 0; tm < 4; tm++) {
            const int r0 = m0 + wm * 64 + tm * 16 + g;
            const int r1 = r0 + 8;
            if (r0 < NQ) {
                float2 o = make_float2(acc[tm][tn][0] + bv.x, acc[tm][tn][1] + bv.y);
                *(float2*)&g_P[(size_t)r0 * N_OUT + outn0 + cl] = o;
            }
            if (r1 < NQ) {
                float2 o = make_float2(acc[tm][tn][2] + bv.x, acc[tm][tn][3] + bv.y);
                *(float2*)&g_P[(size_t)r1 * N_OUT + outn0 + cl] = o;
            }
        }
    }
}

// ---------------------------------------------------------------------------
// Sampling v5 (unchanged from R9: 77.7us, occ 92%, at L1 ceiling).
// ---------------------------------------------------------------------------
__global__ __launch_bounds__(512) void msda_sample_kernel(
    const float* __restrict__ ref,    // (2, LEN_Q, 4, 2)
    float* __restrict__ out)          // (2, LEN_Q, 256)
{
    __shared__ float4 s_w[RB][8][17];   // padded: head stride 17
    __shared__ int    s_i[RB][8][17];

    const int row0 = blockIdx.x * RB;
    const int t    = threadIdx.x;

    // ---------------- Phase 1: 8 threads per (row, head), 2 points each ----
    {
        const int pair = t >> 3;        // 0..63: (row_local, head)
        const int sub  = t & 7;         // 2 points each
        const int rl   = pair >> 3;
        const int h    = pair & 7;
        const int row  = row0 + rl;

        if (row < NQ) {
            const float* Prow = g_P + (size_t)row * N_OUT;

            float lg[16];
#pragma unroll
            for (int v = 0; v < 4; v++) {
                float4 q = *(const float4*)&Prow[256 + h * 16 + v * 4];
                lg[v*4+0] = q.x; lg[v*4+1] = q.y; lg[v*4+2] = q.z; lg[v*4+3] = q.w;
            }
            float mx = lg[0];
#pragma unroll
            for (int v = 1; v < 16; v++) mx = fmaxf(mx, lg[v]);
            float ssum = 0.f;
#pragma unroll
            for (int v = 0; v < 16; v++) ssum += __expf(lg[v] - mx);
            const float inv = 1.f / ssum;

#pragma unroll
            for (int jj = 0; jj < 2; jj++) {
                const int j = sub * 2 + jj;
                const int l = j >> 2;
                const int D = (l == 0) ? 100 : (l == 1) ? 50 : (l == 2) ? 25 : 13;

                const float wgt  = __expf(lg[j] - mx) * inv;
                const float offx = Prow[h * 32 + j * 2];
                const float offy = Prow[h * 32 + j * 2 + 1];
                const float rx = ref[(size_t)(row * 4 + l) * 2 + 0];
                const float ry = ref[(size_t)(row * 4 + l) * 2 + 1];
                const float x = fmaf(rx, (float)D, offx) - 0.5f;
                const float y = fmaf(ry, (float)D, offy) - 0.5f;

                const float xf = floorf(x), yf = floorf(y);
                const int x0 = (int)xf, y0 = (int)yf;
                const float fx = x - xf, fy = y - yf;

                const float gx0 = (x0 >= 0     && x0 < D)     ? (1.f - fx) : 0.f;
                const float gx1 = (x0 + 1 >= 0 && x0 + 1 < D) ? fx         : 0.f;
                const float gy0 = (y0 >= 0     && y0 < D)     ? (1.f - fy) : 0.f;
                const float gy1 = (y0 + 1 >= 0 && y0 + 1 < D) ? fy         : 0.f;

                const int cx = min(max(x0, 0), D - 2);
                const int cy = min(max(y0, 0), D - 2);
                const float wl = (x0 < 0) ? gx1 : ((x0 <= D - 2) ? gx0 : 0.f);
                const float wr = (x0 < 0) ? 0.f : ((x0 <= D - 2) ? gx1 : gx0);
                const float wt = (y0 < 0) ? gy1 : ((y0 <= D - 2) ? gy0 : 0.f);
                const float wb = (y0 < 0) ? 0.f : ((y0 <= D - 2) ? gy1 : gy0);

                s_w[rl][h][j] = make_float4(wgt * wl * wt, wgt * wr * wt,
                                            wgt * wl * wb, wgt * wr * wb);
                s_i[rl][h][j] = cy * D + cx;
            }
        }
    }
    __syncthreads();

    // ---------------- Phase 2: one float4-slot per thread ----------------
    {
        const int rl  = t >> 6;              // 0..7
        const int c4  = t & 63;              // float4 slot: head = c4>>3
        const int row = row0 + rl;
        if (row >= NQ) return;

        const int h = c4 >> 3;
        const int b = (row >= LEN_Q) ? 1 : 0;
        const __half* vb = g_Vh + (size_t)b * LEN_Q * 256 + h * 32 + (c4 & 7) * 4;

        float4 acc = make_float4(0.f, 0.f, 0.f, 0.f);
#pragma unroll
        for (int j = 0; j < 16; j++) {
            const int l    = j >> 2;                          // compile-time
            const int DD   = (l == 0) ? 100 : (l == 1) ? 50 : (l == 2) ? 25 : 13;
            const int BASE = (l == 0) ? 0 : (l == 1) ? 10000 : (l == 2) ? 12500 : 13125;

            const float4 w  = s_w[rl][h][j];
            const int    ix = s_i[rl][h][j];
            const __half* p = vb + (size_t)(BASE + ix) * 256;

            const uint2 u00 = *(const uint2*)p;
            const uint2 u01 = *(const uint2*)(p + 256);
            const uint2 u10 = *(const uint2*)(p + DD * 256);
            const uint2 u11 = *(const uint2*)(p + DD * 256 + 256);

            const float2 a00 = __half22float2(*(const __half2*)&u00.x);
            const float2 b00 = __half22float2(*(const __half2*)&u00.y);
            const float2 a01 = __half22float2(*(const __half2*)&u01.x);
            const float2 b01 = __half22float2(*(const __half2*)&u01.y);
            const float2 a10 = __half22float2(*(const __half2*)&u10.x);
            const float2 b10 = __half22float2(*(const __half2*)&u10.y);
            const float2 a11 = __half22float2(*(const __half2*)&u11.x);
            const float2 b11 = __half22float2(*(const __half2*)&u11.y);

            acc.x = fmaf(w.x, a00.x, acc.x);
            acc.y = fmaf(w.x, a00.y, acc.y);
            acc.z = fmaf(w.x, b00.x, acc.z);
            acc.w = fmaf(w.x, b00.y, acc.w);
            acc.x = fmaf(w.y, a01.x, acc.x);
            acc.y = fmaf(w.y, a01.y, acc.y);
            acc.z = fmaf(w.y, b01.x, acc.z);
            acc.w = fmaf(w.y, b01.y, acc.w);
            acc.x = fmaf(w.z, a10.x, acc.x);
            acc.y = fmaf(w.z, a10.y, acc.y);
            acc.z = fmaf(w.z, b10.x, acc.z);
            acc.w = fmaf(w.z, b10.y, acc.w);
            acc.x = fmaf(w.w, a11.x, acc.x);
            acc.y = fmaf(w.w, a11.y, acc.y);
            acc.z = fmaf(w.w, b11.x, acc.z);
            acc.w = fmaf(w.w, b11.y, acc.w);
        }

        *(float4*)&out[(size_t)row * 256 + c4 * 4] = acc;
    }
}

// ---------------------------------------------------------------------------
extern "C" void kernel_launch(void* const* d_in, const int* in_sizes, int n_in,
                              void* d_out, int out_size)
{
    const float* query = (const float*)d_in[0];   // (2, LEN_Q, 256)
    const float* ref   = (const float*)d_in[1];   // (2, LEN_Q, 4, 2)
    const float* value = (const float*)d_in[2];   // (2, LEN_Q, 256)
    const float* Woff  = (const float*)d_in[3];   // (256, 256)
    const float* boff  = (const float*)d_in[4];   // (256,)
    const float* Wattn = (const float*)d_in[5];   // (256, 128)
    const float* battn = (const float*)d_in[6];   // (128,)
    float* out = (float*)d_out;                   // (2, LEN_Q, 256)

    msda_gemm_cvt_kernel<<<GEMM_BLOCKS + CVT_BLOCKS, 256>>>(
        query, Woff, boff, Wattn, battn, value);

    const int nblocks = (NQ + RB - 1) / RB;       // 3324
    msda_sample_kernel<<<nblocks, 512>>>(ref, out);
}

// round 15
// speedup vs baseline: 1.0628x; 1.0327x over previous
#include <cuda_runtime.h>
#include <cuda_fp16.h>

#define LEN_Q   13294
#define NQ      (2 * LEN_Q)     // 26588 rows (b*LEN_Q + q)
#define N_OUT   384             // 256 offset cols + 128 attn cols
#define RB      8               // rows per sampler block (512 threads)
#define GEMM_MBLKS 416          // ceil(NQ/64)
#define GEMM_BLOCKS (GEMM_MBLKS * 3)
#define CVT_BLOCKS  (NQ * 256 / 4 / 256)   // 6647 exactly

#define LDA 20     // 16 + 4 pad (floats)
#define LDB 132    // 128 + 4 pad (floats)

// Scratch: projection output P[NQ][384]; fp16 copy of value
__device__ float  g_P[NQ * N_OUT];
__device__ __half g_Vh[(size_t)NQ * 256];

// ---------------------------------------------------------------------------
// tf32 / cp.async helpers
// ---------------------------------------------------------------------------
__device__ __forceinline__ unsigned f2tf32(float f) {
    unsigned u;
    asm("cvt.rna.tf32.f32 %0, %1;" : "=r"(u) : "f"(f));
    return u;
}
__device__ __forceinline__ void mma_tf32(float* d, const unsigned* a, const unsigned* b) {
    asm volatile(
        "mma.sync.aligned.m16n8k8.row.col.f32.tf32.tf32.f32 "
        "{%0,%1,%2,%3}, {%4,%5,%6,%7}, {%8,%9}, {%0,%1,%2,%3};"
        : "+f"(d[0]), "+f"(d[1]), "+f"(d[2]), "+f"(d[3])
        : "r"(a[0]), "r"(a[1]), "r"(a[2]), "r"(a[3]),
          "r"(b[0]), "r"(b[1]));
}
__device__ __forceinline__ unsigned smem_u32(const void* p) {
    return (unsigned)__cvta_generic_to_shared(p);
}
__device__ __forceinline__ void cp_async16(unsigned dst, const void* src, int src_bytes) {
    asm volatile("cp.async.cg.shared.global [%0], [%1], 16, %2;"
                 :: "r"(dst), "l"(src), "r"(src_bytes));
}
__device__ __forceinline__ void cp_commit() {
    asm volatile("cp.async.commit_group;");
}
template <int N>
__device__ __forceinline__ void cp_wait() {
    asm volatile("cp.async.wait_group %0;" :: "n"(N));
}

// ---------------------------------------------------------------------------
// Fused kernel: blocks [0, GEMM_BLOCKS) = tf32 GEMM; rest = value fp32->fp16.
// GEMM v8: BM=64, BN=128, warp tile 32x32 (acc 32 regs/thread) -> ~3 blocks/SM
// (75% occ) for latency hiding. R9 double-buffer pipeline + numerics.
// ---------------------------------------------------------------------------
__global__ __launch_bounds__(256) void msda_gemm_cvt_kernel(
    const float* __restrict__ Q,
    const float* __restrict__ Woff, const float* __restrict__ boff,
    const float* __restrict__ Wattn, const float* __restrict__ battn,
    const float* __restrict__ value)
{
    // ---- cvt part -----------------------------------------------------
    if (blockIdx.x >= GEMM_BLOCKS) {
        const int i = (blockIdx.x - GEMM_BLOCKS) * 256 + threadIdx.x;  // float4 idx
        const float4 f = ((const float4*)value)[i];
        __half2* dst = (__half2*)g_Vh + (size_t)i * 2;
        dst[0] = __floats2half2_rn(f.x, f.y);
        dst[1] = __floats2half2_rn(f.z, f.w);
        return;
    }

    // ---- GEMM part ----------------------------------------------------
    __shared__ float As[2][64 * LDA];    // [m][k]  64 rows
    __shared__ float Bs[2][16 * LDB];    // [k][n]

    const int mblk = blockIdx.x % GEMM_MBLKS;
    const int nblk = blockIdx.x / GEMM_MBLKS;
    const int m0   = mblk * 64;

    const float* W; const float* bias; int ldW, n0;
    if (nblk < 2) { W = Woff;  bias = boff + nblk * 128; ldW = 256; n0 = nblk * 128; }
    else          { W = Wattn; bias = battn;             ldW = 128; n0 = 0;          }
    const int outn0 = nblk * 128;

    const int tid  = threadIdx.x;
    const int wid  = tid >> 5;
    const int lane = tid & 31;
    const int g    = lane >> 2;
    const int tig  = lane & 3;
    const int wm   = wid & 1;          // rows wm*32
    const int wn   = wid >> 1;         // cols wn*32

    // A tile: 64x16 floats = 256 chunks of 16B -> 1 per thread
    const int ar  = tid >> 2,  ak  = (tid & 3) * 4;
    // B tile: 16x128 floats = 512 chunks -> 2 per thread
    const int bc0r = tid >> 5,         bc0c = (tid & 31) * 4;
    const int bc1r = (tid + 256) >> 5, bc1c = ((tid + 256) & 31) * 4;

    const unsigned sA[2] = { smem_u32(&As[0][0]), smem_u32(&As[1][0]) };
    const unsigned sB[2] = { smem_u32(&Bs[0][0]), smem_u32(&Bs[1][0]) };

    auto load_tile = [&](int s, int k0) {
        int v0 = (m0 + ar < NQ) ? 16 : 0;
        cp_async16(sA[s] + (ar * LDA + ak) * 4,
                   &Q[(size_t)(m0 + ar) * 256 + k0 + ak], v0);
        cp_async16(sB[s] + (bc0r * LDB + bc0c) * 4,
                   &W[(size_t)(k0 + bc0r) * ldW + n0 + bc0c], 16);
        cp_async16(sB[s] + (bc1r * LDB + bc1c) * 4,
                   &W[(size_t)(k0 + bc1r) * ldW + n0 + bc1c], 16);
        cp_commit();
    };

    float acc[2][4][4];
#pragma unroll
    for (int tm = 0; tm < 2; tm++)
#pragma unroll
        for (int tn = 0; tn < 4; tn++)
#pragma unroll
            for (int r = 0; r < 4; r++) acc[tm][tn][r] = 0.f;

    load_tile(0, 0);

#pragma unroll 1
    for (int it = 0; it < 16; it++) {
        const int s = it & 1;
        if (it + 1 < 16) {
            load_tile(1 - s, (it + 1) * 16);
            cp_wait<1>();
        } else {
            cp_wait<0>();
        }
        __syncthreads();

        const float* Ab = &As[s][0];
        const float* Bb = &Bs[s][0];
#pragma unroll
        for (int ks = 0; ks < 2; ks++) {
            const int kk = ks * 8;
            unsigned af[2][4];
#pragma unroll
            for (int tm = 0; tm < 2; tm++) {
                const int r = wm * 32 + tm * 16;
                af[tm][0] = f2tf32(Ab[(r + g)     * LDA + kk + tig]);
                af[tm][1] = f2tf32(Ab[(r + g + 8) * LDA + kk + tig]);
                af[tm][2] = f2tf32(Ab[(r + g)     * LDA + kk + tig + 4]);
                af[tm][3] = f2tf32(Ab[(r + g + 8) * LDA + kk + tig + 4]);
            }
            unsigned bf[4][2];
#pragma unroll
            for (int tn = 0; tn < 4; tn++) {
                const int c = wn * 32 + tn * 8;
                bf[tn][0] = f2tf32(Bb[(kk + tig)     * LDB + c + g]);
                bf[tn][1] = f2tf32(Bb[(kk + tig + 4) * LDB + c + g]);
            }
#pragma unroll
            for (int tm = 0; tm < 2; tm++)
#pragma unroll
                for (int tn = 0; tn < 4; tn++)
                    mma_tf32(acc[tm][tn], af[tm], bf[tn]);
        }
        __syncthreads();
    }

#pragma unroll
    for (int tn = 0; tn < 4; tn++) {
        const int cl = wn * 32 + tn * 8 + tig * 2;
        const float2 bv = *(const float2*)&bias[cl];
#pragma unroll
        for (int tm = 0; tm < 2; tm++) {
            const int r0 = m0 + wm * 32 + tm * 16 + g;
            const int r1 = r0 + 8;
            if (r0 < NQ) {
                float2 o = make_float2(acc[tm][tn][0] + bv.x, acc[tm][tn][1] + bv.y);
                *(float2*)&g_P[(size_t)r0 * N_OUT + outn0 + cl] = o;
            }
            if (r1 < NQ) {
                float2 o = make_float2(acc[tm][tn][2] + bv.x, acc[tm][tn][3] + bv.y);
                *(float2*)&g_P[(size_t)r1 * N_OUT + outn0 + cl] = o;
            }
        }
    }
}

// ---------------------------------------------------------------------------
// Sampling v5 (unchanged from R9/R14: 74.6us, occ 92%, at L1 ceiling).
// ---------------------------------------------------------------------------
__global__ __launch_bounds__(512) void msda_sample_kernel(
    const float* __restrict__ ref,    // (2, LEN_Q, 4, 2)
    float* __restrict__ out)          // (2, LEN_Q, 256)
{
    __shared__ float4 s_w[RB][8][17];   // padded: head stride 17
    __shared__ int    s_i[RB][8][17];

    const int row0 = blockIdx.x * RB;
    const int t    = threadIdx.x;

    // ---------------- Phase 1: 8 threads per (row, head), 2 points each ----
    {
        const int pair = t >> 3;        // 0..63: (row_local, head)
        const int sub  = t & 7;         // 2 points each
        const int rl   = pair >> 3;
        const int h    = pair & 7;
        const int row  = row0 + rl;

        if (row < NQ) {
            const float* Prow = g_P + (size_t)row * N_OUT;

            float lg[16];
#pragma unroll
            for (int v = 0; v < 4; v++) {
                float4 q = *(const float4*)&Prow[256 + h * 16 + v * 4];
                lg[v*4+0] = q.x; lg[v*4+1] = q.y; lg[v*4+2] = q.z; lg[v*4+3] = q.w;
            }
            float mx = lg[0];
#pragma unroll
            for (int v = 1; v < 16; v++) mx = fmaxf(mx, lg[v]);
            float ssum = 0.f;
#pragma unroll
            for (int v = 0; v < 16; v++) ssum += __expf(lg[v] - mx);
            const float inv = 1.f / ssum;

#pragma unroll
            for (int jj = 0; jj < 2; jj++) {
                const int j = sub * 2 + jj;
                const int l = j >> 2;
                const int D = (l == 0) ? 100 : (l == 1) ? 50 : (l == 2) ? 25 : 13;

                const float wgt  = __expf(lg[j] - mx) * inv;
                const float offx = Prow[h * 32 + j * 2];
                const float offy = Prow[h * 32 + j * 2 + 1];
                const float rx = ref[(size_t)(row * 4 + l) * 2 + 0];
                const float ry = ref[(size_t)(row * 4 + l) * 2 + 1];
                const float x = fmaf(rx, (float)D, offx) - 0.5f;
                const float y = fmaf(ry, (float)D, offy) - 0.5f;

                const float xf = floorf(x), yf = floorf(y);
                const int x0 = (int)xf, y0 = (int)yf;
                const float fx = x - xf, fy = y - yf;

                const float gx0 = (x0 >= 0     && x0 < D)     ? (1.f - fx) : 0.f;
                const float gx1 = (x0 + 1 >= 0 && x0 + 1 < D) ? fx         : 0.f;
                const float gy0 = (y0 >= 0     && y0 < D)     ? (1.f - fy) : 0.f;
                const float gy1 = (y0 + 1 >= 0 && y0 + 1 < D) ? fy         : 0.f;

                const int cx = min(max(x0, 0), D - 2);
                const int cy = min(max(y0, 0), D - 2);
                const float wl = (x0 < 0) ? gx1 : ((x0 <= D - 2) ? gx0 : 0.f);
                const float wr = (x0 < 0) ? 0.f : ((x0 <= D - 2) ? gx1 : gx0);
                const float wt = (y0 < 0) ? gy1 : ((y0 <= D - 2) ? gy0 : 0.f);
                const float wb = (y0 < 0) ? 0.f : ((y0 <= D - 2) ? gy1 : gy0);

                s_w[rl][h][j] = make_float4(wgt * wl * wt, wgt * wr * wt,
                                            wgt * wl * wb, wgt * wr * wb);
                s_i[rl][h][j] = cy * D + cx;
            }
        }
    }
    __syncthreads();

    // ---------------- Phase 2: one float4-slot per thread ----------------
    {
        const int rl  = t >> 6;              // 0..7
        const int c4  = t & 63;              // float4 slot: head = c4>>3
        const int row = row0 + rl;
        if (row >= NQ) return;

        const int h = c4 >> 3;
        const int b = (row >= LEN_Q) ? 1 : 0;
        const __half* vb = g_Vh + (size_t)b * LEN_Q * 256 + h * 32 + (c4 & 7) * 4;

        float4 acc = make_float4(0.f, 0.f, 0.f, 0.f);
#pragma unroll
        for (int j = 0; j < 16; j++) {
            const int l    = j >> 2;                          // compile-time
            const int DD   = (l == 0) ? 100 : (l == 1) ? 50 : (l == 2) ? 25 : 13;
            const int BASE = (l == 0) ? 0 : (l == 1) ? 10000 : (l == 2) ? 12500 : 13125;

            const float4 w  = s_w[rl][h][j];
            const int    ix = s_i[rl][h][j];
            const __half* p = vb + (size_t)(BASE + ix) * 256;

            const uint2 u00 = *(const uint2*)p;
            const uint2 u01 = *(const uint2*)(p + 256);
            const uint2 u10 = *(const uint2*)(p + DD * 256);
            const uint2 u11 = *(const uint2*)(p + DD * 256 + 256);

            const float2 a00 = __half22float2(*(const __half2*)&u00.x);
            const float2 b00 = __half22float2(*(const __half2*)&u00.y);
            const float2 a01 = __half22float2(*(const __half2*)&u01.x);
            const float2 b01 = __half22float2(*(const __half2*)&u01.y);
            const float2 a10 = __half22float2(*(const __half2*)&u10.x);
            const float2 b10 = __half22float2(*(const __half2*)&u10.y);
            const float2 a11 = __half22float2(*(const __half2*)&u11.x);
            const float2 b11 = __half22float2(*(const __half2*)&u11.y);

            acc.x = fmaf(w.x, a00.x, acc.x);
            acc.y = fmaf(w.x, a00.y, acc.y);
            acc.z = fmaf(w.x, b00.x, acc.z);
            acc.w = fmaf(w.x, b00.y, acc.w);
            acc.x = fmaf(w.y, a01.x, acc.x);
            acc.y = fmaf(w.y, a01.y, acc.y);
            acc.z = fmaf(w.y, b01.x, acc.z);
            acc.w = fmaf(w.y, b01.y, acc.w);
            acc.x = fmaf(w.z, a10.x, acc.x);
            acc.y = fmaf(w.z, a10.y, acc.y);
            acc.z = fmaf(w.z, b10.x, acc.z);
            acc.w = fmaf(w.z, b10.y, acc.w);
            acc.x = fmaf(w.w, a11.x, acc.x);
            acc.y = fmaf(w.w, a11.y, acc.y);
            acc.z = fmaf(w.w, b11.x, acc.z);
            acc.w = fmaf(w.w, b11.y, acc.w);
        }

        *(float4*)&out[(size_t)row * 256 + c4 * 4] = acc;
    }
}

// ---------------------------------------------------------------------------
extern "C" void kernel_launch(void* const* d_in, const int* in_sizes, int n_in,
                              void* d_out, int out_size)
{
    const float* query = (const float*)d_in[0];   // (2, LEN_Q, 256)
    const float* ref   = (const float*)d_in[1];   // (2, LEN_Q, 4, 2)
    const float* value = (const float*)d_in[2];   // (2, LEN_Q, 256)
    const float* Woff  = (const float*)d_in[3];   // (256, 256)
    const float* boff  = (const float*)d_in[4];   // (256,)
    const float* Wattn = (const float*)d_in[5];   // (256, 128)
    const float* battn = (const float*)d_in[6];   // (128,)
    float* out = (float*)d_out;                   // (2, LEN_Q, 256)

    msda_gemm_cvt_kernel<<<GEMM_BLOCKS + CVT_BLOCKS, 256>>>(
        query, Woff, boff, Wattn, battn, value);

    const int nblocks = (NQ + RB - 1) / RB;       // 3324
    msda_sample_kernel<<<nblocks, 512>>>(ref, out);
}